// round 13
// baseline (speedup 1.0000x reference)
#include <cuda_runtime.h>
#include <cuda_fp16.h>
#include <math.h>

#define IMG     512
#define NVIEW   360
#define NQUADX  91           // 0..88 full quads; 89 -> pair {89,269}; 90 -> pair {179,359}
#define NQ      32           // row-slices per quad
#define RQ      (IMG / NQ)   // 16 rows per CTA
#define PW      516          // gmem line stride (entries 0..513 valid)
#define N1      (514 * PW)
#define OUTN    (2 * IMG * NVIEW)

// fp16 dup-pair images, batch-interleaved half2(b0,b1), zeros baked into borders.
// Quad of views {v, v+180, 358-v, 178-v} all sample view-v geometry on images
//   I,  J[r][c]=I[511-c][r],  K[r][c]=I[r][511-c],  L[r][c]=I[511-c][511-r].
// Entry i of line p packs (lo=pixel i-1, hi=pixel i): ij = (I_lo,I_hi,J_lo,J_hi),
// kl = (K_lo,K_hi,L_lo,L_hi). Row orientation: line p = image row p-1 (i over x);
// col orientation: line p = image col p-1 (i over y).
__device__ uint4 g_ij_r[N1], g_kl_r[N1];
__device__ uint4 g_ij_c[N1], g_kl_c[N1];
__device__ float4 g_vp[NVIEW];
__device__ int    g_vmode[NVIEW];

__device__ __forceinline__ unsigned h2pix(const float* __restrict__ x, int y, int xx) {
    float2 f = make_float2(0.f, 0.f);
    if ((unsigned)y < 512u && (unsigned)xx < 512u) {
        f.x = x[y * IMG + xx];
        f.y = x[IMG * IMG + y * IMG + xx];
    }
    __half2 h = __float22half2_rn(f);
    return *reinterpret_cast<unsigned*>(&h);
}

__global__ void prep_kernel(const float* __restrict__ x, float* __restrict__ out) {
    int idx = blockIdx.x * blockDim.x + threadIdx.x;

    if (idx < NVIEW) {
        double ang = -M_PI * (double)(idx + 1) / (double)NVIEW - M_PI;
        float c = (float)cos(ang);
        float s = (float)sin(ang);
        if (fabsf(c) >= fabsf(s)) g_vp[idx] = make_float4(c, -s, s, c),  g_vmode[idx] = 0;
        else                      g_vp[idx] = make_float4(-s, c, c, s),  g_vmode[idx] = 1;
    }

    if (idx < OUTN) out[idx] = 0.0f;   // fp_kernel accumulates atomically

    if (idx < 2 * N1) {
        int o   = (idx >= N1);
        int rem = idx - o * N1;
        int p   = rem / PW;
        int i   = rem - p * PW;
        if (o == 0) {   // row orientation
            g_ij_r[rem] = make_uint4(h2pix(x, p - 1,   i - 1),   h2pix(x, p - 1,   i),
                                     h2pix(x, 512 - i, p - 1),   h2pix(x, 511 - i, p - 1));
            g_kl_r[rem] = make_uint4(h2pix(x, p - 1,   512 - i), h2pix(x, p - 1,   511 - i),
                                     h2pix(x, 512 - i, 512 - p), h2pix(x, 511 - i, 512 - p));
        } else {        // col orientation
            g_ij_c[rem] = make_uint4(h2pix(x, i - 1,   p - 1),   h2pix(x, i,       p - 1),
                                     h2pix(x, 512 - p, i - 1),   h2pix(x, 512 - p, i));
            g_kl_c[rem] = make_uint4(h2pix(x, i - 1,   512 - p), h2pix(x, i,       512 - p),
                                     h2pix(x, 512 - p, 512 - i), h2pix(x, 512 - p, 511 - i));
        }
    }
}

__device__ __forceinline__ void lerp2(uint4 e, __half2 wqh, float wp,
                                      float& u0, float& u1, float& u2, float& u3) {
    __half2 mA = __hfma2(wqh, __hsub2(*(const __half2*)&e.y, *(const __half2*)&e.x),
                         *(const __half2*)&e.x);
    __half2 mB = __hfma2(wqh, __hsub2(*(const __half2*)&e.w, *(const __half2*)&e.z),
                         *(const __half2*)&e.z);
    float2 fA = __half22float2(mA);
    float2 fB = __half22float2(mB);
    u0 = fmaf(wp, fA.x, u0);
    u1 = fmaf(wp, fA.y, u1);
    u2 = fmaf(wp, fB.x, u2);
    u3 = fmaf(wp, fB.y, u3);
}

__device__ __forceinline__ void cand(const uint4* __restrict__ lij,   // line + 1
                                     const uint4* __restrict__ lkl,
                                     float wp, float Q, float* ac) {
    float Qc = fminf(fmaxf(Q, -1.0f), 512.0f);   // clamp lands on zero pads
    float q0 = floorf(Qc);
    float wq = Qc - q0;
    int   px = (int)q0;                          // lines pre-offset by +1
    uint4 eij = __ldg(&lij[px]);                 // shared index, two coalesced loads
    uint4 ekl = __ldg(&lkl[px]);
    __half2 wqh = __float2half2_rn(wq);
    lerp2(eij, wqh, wp, ac[0], ac[1], ac[2], ac[3]);   // I(b0,b1), J(b0,b1)
    lerp2(ekl, wqh, wp, ac[4], ac[5], ac[6], ac[7]);   // K(b0,b1), L(b0,b1)
}

__global__ __launch_bounds__(512) void fp_kernel(float* __restrict__ out) {
    int bx = blockIdx.x;
    int v  = (bx == 90) ? 179 : bx;   // quad base view
    bool full = (bx < 89);            // bx 89/90: degenerate quads, write I/J only
    int q  = blockIdx.y;
    int w  = threadIdx.x;
    int r0 = q * RQ;

    float4 vp = g_vp[v];
    int mode = g_vmode[v];
    const uint4* __restrict__ Gij = mode ? g_ij_c : g_ij_r;
    const uint4* __restrict__ Gkl = mode ? g_kl_c : g_kl_r;

    float a    = vp.x;
    float bc   = vp.y;
    float absa = fabsf(a);
    float c2   = 1.0f - 2.0f * absa;            // for wp2
    float wr   = (float)w - 255.5f;
    float A    = fmaf(vp.z, wr, 255.5f);
    float B    = fmaf(vp.w, wr, 255.5f);
    float Bp   = fmaf(-255.5f, bc, B);          // Q = bc*hb + Bp
    float inv_a = 1.0f / a;

    float ac[8] = {0.f, 0.f, 0.f, 0.f, 0.f, 0.f, 0.f, 0.f};

    // hc at r = r0, advanced incrementally (drift << window margin)
    float hcv = fmaf((float)r0 - A, inv_a, 255.5f);

    // padded lines for image row r0, pre-offset +1 so px in [-1,512] indexes directly
    const uint4* lij = Gij + (size_t)(r0 + 1) * PW + 1;
    const uint4* lkl = Gkl + (size_t)(r0 + 1) * PW + 1;

    #pragma unroll 2
    for (int st = 0; st < RQ; st++) {
        // hc solves P(h)=r; open support spans < 2*sqrt(2); 3 candidates
        // from hb = ceil(hc - 1.4146) provably cover it.
        float hb = ceilf(hcv - 1.4146f);
        int   h0 = (int)hb;
        float d  = hb - hcv;                  // in (-1.4146, -0.4146]
        float Q  = fmaf(bc, hb, Bp);

        float wp0 = fmaxf(fmaf( absa, d,               1.0f), 0.0f);  // d < 0
        float wp1 = fmaxf(fmaf(-absa, fabsf(d + 1.0f), 1.0f), 0.0f);
        float wp2 = fmaxf(fmaf(-absa, d,               c2),   0.0f);  // = 1-|a|(d+2)

        if ((unsigned)h0 > 509u) {            // rare edge rows
            if ((unsigned)h0       >= 512u) wp0 = 0.0f;
            if ((unsigned)(h0 + 1) >= 512u) wp1 = 0.0f;
            if ((unsigned)(h0 + 2) >= 512u) wp2 = 0.0f;
        }

        cand(lij, lkl, wp0, Q,             ac);
        cand(lij, lkl, wp1, Q + bc,        ac);
        cand(lij, lkl, wp2, Q + 2.0f * bc, ac);

        hcv += inv_a;
        lij += PW;
        lkl += PW;
    }

    int b0 = w * NVIEW;
    int b1 = IMG * NVIEW + w * NVIEW;
    atomicAdd(&out[b0 + v],       ac[0] * 0.5f);
    atomicAdd(&out[b1 + v],       ac[1] * 0.5f);
    atomicAdd(&out[b0 + v + 180], ac[2] * 0.5f);
    atomicAdd(&out[b1 + v + 180], ac[3] * 0.5f);
    if (full) {
        atomicAdd(&out[b0 + 358 - v], ac[4] * 0.5f);
        atomicAdd(&out[b1 + 358 - v], ac[5] * 0.5f);
        atomicAdd(&out[b0 + 178 - v], ac[6] * 0.5f);
        atomicAdd(&out[b1 + 178 - v], ac[7] * 0.5f);
    }
}

extern "C" void kernel_launch(void* const* d_in, const int* in_sizes, int n_in,
                              void* d_out, int out_size) {
    const float* x = (const float*)d_in[0];
    float* out = (float*)d_out;

    int nprep = 2 * N1;   // > OUTN and > NVIEW
    prep_kernel<<<(nprep + 255) / 256, 256>>>(x, out);

    dim3 grid(NQUADX, NQ);
    fp_kernel<<<grid, 512>>>(out);
}

// round 14
// speedup vs baseline: 1.1014x; 1.1014x over previous
#include <cuda_runtime.h>
#include <cuda_fp16.h>
#include <math.h>

#define IMG     512
#define NVIEW   360
#define NPAIR   180          // view pairs (v, v+180): angles differ by exactly pi/2
#define NQ      16           // row-slices per view-pair
#define RQ      (IMG / NQ)   // 32 rows per CTA
#define PW      516          // gmem line stride (entries 0..513 valid)
#define N1      (514 * PW)
#define OUTN    (2 * IMG * NVIEW)

// Interleaved fp16 dup-pair images, batch-interleaved, zeros baked into borders.
// Entry i of padded line p = ( I_lo, I_hi, J_lo, J_hi ) where each is half2(b0,b1),
// lo = pixel i-1, hi = pixel i, and J[r][c] = I[511-c][r] (90-deg rotation pairs
// view v with view v+180 whose angle differs by exactly pi/2).
__device__ uint4 g_ir[N1];   // row orientation
__device__ uint4 g_ic[N1];   // col orientation
__device__ float4 g_vp[NVIEW];
__device__ int    g_vmode[NVIEW];

__device__ __forceinline__ unsigned h2pix(const float* __restrict__ x, int y, int xx) {
    float2 f = make_float2(0.f, 0.f);
    if ((unsigned)y < 512u && (unsigned)xx < 512u) {
        f.x = x[y * IMG + xx];
        f.y = x[IMG * IMG + y * IMG + xx];
    }
    __half2 h = __float22half2_rn(f);
    return *reinterpret_cast<unsigned*>(&h);
}

__global__ void prep_kernel(const float* __restrict__ x, float* __restrict__ out) {
    int idx = blockIdx.x * blockDim.x + threadIdx.x;

    if (idx < NVIEW) {
        double ang = -M_PI * (double)(idx + 1) / (double)NVIEW - M_PI;
        float c = (float)cos(ang);
        float s = (float)sin(ang);
        if (fabsf(c) >= fabsf(s)) g_vp[idx] = make_float4(c, -s, s, c),  g_vmode[idx] = 0;
        else                      g_vp[idx] = make_float4(-s, c, c, s),  g_vmode[idx] = 1;
    }

    if (idx < OUTN) out[idx] = 0.0f;   // fp_kernel accumulates atomically

    if (idx < N1) {
        int p = idx / PW;
        int i = idx - p * PW;
        // row orientation: I part = image row p-1; J part = J row p-1 = I[512-i..][p-1]
        g_ir[idx] = make_uint4(h2pix(x, p - 1,   i - 1), h2pix(x, p - 1,   i),
                               h2pix(x, 512 - i, p - 1), h2pix(x, 511 - i, p - 1));
        // col orientation: I part = image col p-1; J part = J col p-1 = I[512-p][i-1..i]
        g_ic[idx] = make_uint4(h2pix(x, i - 1,   p - 1), h2pix(x, i,       p - 1),
                               h2pix(x, 512 - p, i - 1), h2pix(x, 512 - p, i));
    }
}

__device__ __forceinline__ void lerpacc(uint4 e, float wq, float wp,
                                        float& a0, float& a1, float& a2, float& a3) {
    __half2 wqh = __float2half2_rn(wq);
    __half2 mI = __hfma2(wqh, __hsub2(*(const __half2*)&e.y, *(const __half2*)&e.x),
                         *(const __half2*)&e.x);
    __half2 mJ = __hfma2(wqh, __hsub2(*(const __half2*)&e.w, *(const __half2*)&e.z),
                         *(const __half2*)&e.z);
    float2 fI = __half22float2(mI);
    float2 fJ = __half22float2(mJ);
    a0 = fmaf(wp, fI.x, a0);
    a1 = fmaf(wp, fI.y, a1);
    a2 = fmaf(wp, fJ.x, a2);
    a3 = fmaf(wp, fJ.y, a3);
}

__global__ __launch_bounds__(512) void fp_kernel(float* __restrict__ out) {
    int v = blockIdx.x;               // primary view; pair view = v + 180
    int q = blockIdx.y;
    int w = threadIdx.x;
    int r0 = q * RQ;

    float4 vp = g_vp[v];
    const uint4* __restrict__ G = g_vmode[v] ? g_ic : g_ir;

    float a    = vp.x;
    float bc   = vp.y;
    float absa = fabsf(a);
    float c2   = 1.0f - 2.0f * absa;            // for wp2
    float wr   = (float)w - 255.5f;
    float A    = fmaf(vp.z, wr, 255.5f);
    float B    = fmaf(vp.w, wr, 255.5f);
    float Bp   = fmaf(-255.5f, bc, B);          // Q = bc*hb + Bp
    float inv_a = 1.0f / a;

    float a0 = 0.f, a1 = 0.f, a2 = 0.f, a3 = 0.f;

    // hc at r = r0, advanced incrementally (drift << window margin)
    float hcv = fmaf((float)r0 - A, inv_a, 255.5f);

    // padded line for image row r0, pre-offset by +1 so px in [-1,512] indexes directly
    const uint4* linep = G + (size_t)(r0 + 1) * PW + 1;

    #pragma unroll 4
    for (int st = 0; st < RQ; st++) {
        // hc solves P(h)=r; open support spans < 2*sqrt(2); 3 candidates
        // from hb = ceil(hc - 1.4146) provably cover it.
        float hb = ceilf(hcv - 1.4146f);
        int   h0 = (int)hb;
        float d  = hb - hcv;                  // in (-1.4146, -0.4146]
        float Q0 = fmaf(bc, hb, Bp);
        float Q1 = Q0 + bc;
        float Q2 = Q0 + 2.0f * bc;

        // ---- phase A: addresses + all three loads in flight ----
        float Qc0 = fminf(fmaxf(Q0, -1.0f), 512.0f);   // clamp lands on zero pads
        float Qc1 = fminf(fmaxf(Q1, -1.0f), 512.0f);
        float Qc2 = fminf(fmaxf(Q2, -1.0f), 512.0f);
        float f0 = floorf(Qc0);
        float f1 = floorf(Qc1);
        float f2 = floorf(Qc2);
        uint4 e0 = __ldg(&linep[(int)f0]);
        uint4 e1 = __ldg(&linep[(int)f1]);
        uint4 e2 = __ldg(&linep[(int)f2]);

        // ---- phase B: weights + math ----
        float wp0 = fmaxf(fmaf( absa, d,               1.0f), 0.0f);  // d < 0
        float wp1 = fmaxf(fmaf(-absa, fabsf(d + 1.0f), 1.0f), 0.0f);
        float wp2 = fmaxf(fmaf(-absa, d,               c2),   0.0f);  // = 1-|a|(d+2)

        if ((unsigned)h0 > 509u) {            // rare edge rows
            if ((unsigned)h0       >= 512u) wp0 = 0.0f;
            if ((unsigned)(h0 + 1) >= 512u) wp1 = 0.0f;
            if ((unsigned)(h0 + 2) >= 512u) wp2 = 0.0f;
        }

        lerpacc(e0, Qc0 - f0, wp0, a0, a1, a2, a3);
        lerpacc(e1, Qc1 - f1, wp1, a0, a1, a2, a3);
        lerpacc(e2, Qc2 - f2, wp2, a0, a1, a2, a3);

        hcv += inv_a;
        linep += PW;
    }

    int v2 = v + NPAIR;
    atomicAdd(&out[w * NVIEW + v],                a0 * 0.5f);
    atomicAdd(&out[IMG * NVIEW + w * NVIEW + v],  a1 * 0.5f);
    atomicAdd(&out[w * NVIEW + v2],               a2 * 0.5f);
    atomicAdd(&out[IMG * NVIEW + w * NVIEW + v2], a3 * 0.5f);
}

extern "C" void kernel_launch(void* const* d_in, const int* in_sizes, int n_in,
                              void* d_out, int out_size) {
    const float* x = (const float*)d_in[0];
    float* out = (float*)d_out;

    int nprep = OUTN;   // >= N1 and >= NVIEW
    prep_kernel<<<(nprep + 255) / 256, 256>>>(x, out);

    dim3 grid(NPAIR, NQ);
    fp_kernel<<<grid, 512>>>(out);
}